// round 4
// baseline (speedup 1.0000x reference)
#include <cuda_runtime.h>
#include <math.h>

#define Bc 4
#define Lc 1024
#define Kc 30
#define Dc 256
#define Hc 8
#define DKc 32

#define M1c (Bc*Lc)          // 4096
#define M2c (Bc*Lc*Kc)       // 122880

// ---------------- scratch (static device globals; no allocations) ----------------
__device__ float g_q[M1c*Dc];
__device__ float g_k[M1c*Dc];
__device__ float g_v[M1c*Dc];
__device__ float g_bias[Bc*Lc*Lc];              // 16 MB
__device__ float g_S[Bc*Hc*Lc*Lc];              // 128 MB attention logits/probs
__device__ float g_ctx[M1c*Dc];
__device__ float g_tmp[M1c*Dc];
__device__ float g_hvp[M1c*Dc];                 // h_V_new @ W11[0:256] + b11
__device__ float g_m1[M2c*Dc];                  // 126 MB
__device__ float g_m2[M2c*Dc];                  // 126 MB
__device__ float g_base;

// ---------------- packed f32x2 helpers ----------------
typedef unsigned long long u64;

__device__ __forceinline__ u64 pack2(float x, float y) {
    u64 r;
    asm("mov.b64 %0, {%1, %2};" : "=l"(r) : "f"(x), "f"(y));
    return r;
}
__device__ __forceinline__ void fma2(u64& d, u64 a, u64 b) {
    asm("fma.rn.f32x2 %0, %1, %2, %0;" : "+l"(d) : "l"(a), "l"(b));
}
__device__ __forceinline__ float2 unpack2(u64 v) {
    float2 f;
    asm("mov.b64 {%0, %1}, %2;" : "=f"(f.x), "=f"(f.y) : "l"(v));
    return f;
}

// ---------------- reduction helpers ----------------
__device__ __forceinline__ float blockSum(float v, float* sh) {
    int lane = threadIdx.x & 31, wid = threadIdx.x >> 5;
#pragma unroll
    for (int o = 16; o; o >>= 1) v += __shfl_down_sync(0xffffffffu, v, o);
    if (lane == 0) sh[wid] = v;
    __syncthreads();
    if (wid == 0) {
        float r = (lane < 8) ? sh[lane] : 0.f;
#pragma unroll
        for (int o = 4; o; o >>= 1) r += __shfl_down_sync(0xffffffffu, r, o);
        if (lane == 0) sh[0] = r;
    }
    __syncthreads();
    float out = sh[0];
    __syncthreads();
    return out;
}

__device__ __forceinline__ float blockMax(float v, float* sh) {
    int lane = threadIdx.x & 31, wid = threadIdx.x >> 5;
#pragma unroll
    for (int o = 16; o; o >>= 1) v = fmaxf(v, __shfl_down_sync(0xffffffffu, v, o));
    if (lane == 0) sh[wid] = v;
    __syncthreads();
    if (wid == 0) {
        float r = (lane < 8) ? sh[lane] : -3.0e38f;
#pragma unroll
        for (int o = 4; o; o >>= 1) r = fmaxf(r, __shfl_down_sync(0xffffffffu, r, o));
        if (lane == 0) sh[0] = r;
    }
    __syncthreads();
    float out = sh[0];
    __syncthreads();
    return out;
}

__device__ __forceinline__ float gelu_exact(float x) {
    return 0.5f * x * (1.0f + erff(x * 0.70710678118654752f));
}

// ---------------- bias base / fill / scatter ----------------
__global__ void bias_base_kernel(const float* __restrict__ nonE,
                                 const float* __restrict__ bias_W,
                                 const float* __restrict__ bias_b) {
    __shared__ float sh[8];
    int t = threadIdx.x;
    float p = nonE[t] * bias_W[t];
    float s = blockSum(p, sh);
    if (t == 0) g_base = s + bias_b[0];
}

__global__ void bias_fill_kernel() {
    int i = blockIdx.x * 256 + threadIdx.x;
    g_bias[i] = g_base;
}

// one warp per (b,l); k loop serial on lane 0 => last write wins for duplicate idx
__global__ void bias_scatter_kernel(const float* __restrict__ E,
                                    const int* __restrict__ E_idx,
                                    const float* __restrict__ bias_W,
                                    const float* __restrict__ bias_b) {
    int w = (blockIdx.x * blockDim.x + threadIdx.x) >> 5;
    int lane = threadIdx.x & 31;
    if (w >= Bc * Lc) return;
    float bb = bias_b[0];
    for (int k = 0; k < Kc; k++) {
        const float* er = E + (w * Kc + k) * Dc;
        float p = 0.f;
#pragma unroll
        for (int c = lane; c < Dc; c += 32) p += er[c] * bias_W[c];
#pragma unroll
        for (int o = 16; o; o >>= 1) p += __shfl_down_sync(0xffffffffu, p, o);
        if (lane == 0) {
            int idx = E_idx[w * Kc + k];
            g_bias[w * Lc + idx] = p + bb;
        }
    }
}

// ---------------- 64x64 tiled fp32 GEMM with f32x2 (small M GEMMs) ----------------
__global__ void gemm64(const float* __restrict__ A, const float* __restrict__ Bm,
                       float* __restrict__ C, int M, int N, int Kd,
                       const float* __restrict__ bias, int act) {
    __shared__ float As[64][17];
    __shared__ float Bs[16][64];
    int t = threadIdx.x;
    int tx = t & 15, ty = t >> 4;
    int m0 = blockIdx.y * 64, n0 = blockIdx.x * 64;
    u64 acc[4][2] = {};
    for (int k0 = 0; k0 < Kd; k0 += 16) {
#pragma unroll
        for (int i = 0; i < 4; i++) {
            int e = t + i * 256; int r = e >> 4, c = e & 15;
            As[r][c] = A[(size_t)(m0 + r) * Kd + k0 + c];
        }
#pragma unroll
        for (int i = 0; i < 4; i++) {
            int e = t + i * 256; int kk = e >> 6, c = e & 63;
            Bs[kk][c] = Bm[(size_t)(k0 + kk) * N + n0 + c];
        }
        __syncthreads();
#pragma unroll
        for (int kk = 0; kk < 16; kk++) {
            ulonglong2 bb = *reinterpret_cast<const ulonglong2*>(&Bs[kk][tx * 4]);
#pragma unroll
            for (int i = 0; i < 4; i++) {
                float a = As[ty * 4 + i][kk];
                u64 aa = pack2(a, a);
                fma2(acc[i][0], aa, bb.x);
                fma2(acc[i][1], aa, bb.y);
            }
        }
        __syncthreads();
    }
#pragma unroll
    for (int i = 0; i < 4; i++) {
        int row = m0 + ty * 4 + i;
#pragma unroll
        for (int j = 0; j < 2; j++) {
            float2 v = unpack2(acc[i][j]);
            int col = n0 + tx * 4 + j * 2;
            float x0 = v.x + (bias ? bias[col] : 0.f);
            float x1 = v.y + (bias ? bias[col + 1] : 0.f);
            if (act == 1) { x0 = gelu_exact(x0); x1 = gelu_exact(x1); }
            C[(size_t)row * N + col] = x0;
            C[(size_t)row * N + col + 1] = x1;
        }
    }
}

// ---------------- 128x128 tiled fp32 GEMM with f32x2 (big MLP GEMMs) ----------------
// M%128==0, N%128==0, Kd%16==0
__global__ void __launch_bounds__(256, 2)
gemm128(const float* __restrict__ A, const float* __restrict__ Bm,
        float* __restrict__ C, int M, int N, int Kd,
        const float* __restrict__ bias, int act) {
    __shared__ float As[16][132];   // [kk][row]
    __shared__ float Bs[16][128];   // [kk][col]
    int t = threadIdx.x;
    int tx = t & 15, ty = t >> 4;
    int m0 = blockIdx.y * 128, n0 = blockIdx.x * 128;
    const float* Ablk = A + (size_t)m0 * Kd;
    const float* Bblk = Bm + n0;
    u64 acc[8][4] = {};
    for (int k0 = 0; k0 < Kd; k0 += 16) {
        float4 av[2], bv[2];
#pragma unroll
        for (int i = 0; i < 2; i++) {
            int f = t * 2 + i;                 // 0..511
            int r = f >> 2, c4 = f & 3;
            av[i] = *reinterpret_cast<const float4*>(Ablk + (size_t)r * Kd + k0 + c4 * 4);
            int kk = f >> 5, c = (f & 31) * 4;
            bv[i] = *reinterpret_cast<const float4*>(Bblk + (size_t)(k0 + kk) * N + c);
        }
        __syncthreads();
#pragma unroll
        for (int i = 0; i < 2; i++) {
            int f = t * 2 + i;
            int r = f >> 2, c4 = (f & 3) * 4;
            As[c4 + 0][r] = av[i].x;
            As[c4 + 1][r] = av[i].y;
            As[c4 + 2][r] = av[i].z;
            As[c4 + 3][r] = av[i].w;
            int kk = f >> 5, c = (f & 31) * 4;
            *reinterpret_cast<float4*>(&Bs[kk][c]) = bv[i];
        }
        __syncthreads();
#pragma unroll
        for (int kk = 0; kk < 16; kk++) {
            float4 a0 = *reinterpret_cast<const float4*>(&As[kk][ty * 8]);
            float4 a1 = *reinterpret_cast<const float4*>(&As[kk][ty * 8 + 4]);
            ulonglong2 b0 = *reinterpret_cast<const ulonglong2*>(&Bs[kk][tx * 8]);
            ulonglong2 b1 = *reinterpret_cast<const ulonglong2*>(&Bs[kk][tx * 8 + 4]);
            float a[8] = {a0.x, a0.y, a0.z, a0.w, a1.x, a1.y, a1.z, a1.w};
#pragma unroll
            for (int i = 0; i < 8; i++) {
                u64 aa = pack2(a[i], a[i]);
                fma2(acc[i][0], aa, b0.x);
                fma2(acc[i][1], aa, b0.y);
                fma2(acc[i][2], aa, b1.x);
                fma2(acc[i][3], aa, b1.y);
            }
        }
    }
#pragma unroll
    for (int i = 0; i < 8; i++) {
        int row = m0 + ty * 8 + i;
        float o[8];
#pragma unroll
        for (int j = 0; j < 4; j++) {
            float2 v = unpack2(acc[i][j]);
            o[j * 2] = v.x; o[j * 2 + 1] = v.y;
        }
        int col = n0 + tx * 8;
#pragma unroll
        for (int j = 0; j < 8; j++) {
            float x = o[j] + (bias ? bias[col + j] : 0.f);
            if (act == 1) x = gelu_exact(x);
            o[j] = x;
        }
        float4* cp = reinterpret_cast<float4*>(C + (size_t)row * N + col);
        cp[0] = make_float4(o[0], o[1], o[2], o[3]);
        cp[1] = make_float4(o[4], o[5], o[6], o[7]);
    }
}

// ---------------- logits: per (b,h) q@k^T * scale + bias (f32x2) ----------------
__global__ void logits_kernel() {
    __shared__ float As[64][33];
    __shared__ float Bs[32][68];
    int t = threadIdx.x;
    int tx = t & 15, ty = t >> 4;
    int n0 = blockIdx.x * 64, m0 = blockIdx.y * 64;
    int bh = blockIdx.z; int b = bh >> 3, h = bh & 7;
    const float* qb = g_q + (b * Lc) * Dc + h * DKc;
    const float* kb = g_k + (b * Lc) * Dc + h * DKc;
#pragma unroll
    for (int i = 0; i < 8; i++) {
        int e = t + i * 256; int r = e >> 5, c = e & 31;
        As[r][c] = qb[(size_t)(m0 + r) * Dc + c];
    }
#pragma unroll
    for (int i = 0; i < 8; i++) {
        int e = t + i * 256; int n = e >> 5, c = e & 31;
        Bs[c][n] = kb[(size_t)(n0 + n) * Dc + c];
    }
    __syncthreads();
    u64 acc[4][2] = {};
#pragma unroll
    for (int kk = 0; kk < 32; kk++) {
        ulonglong2 bb = *reinterpret_cast<const ulonglong2*>(&Bs[kk][tx * 4]);
#pragma unroll
        for (int i = 0; i < 4; i++) {
            float a = As[ty * 4 + i][kk];
            u64 aa = pack2(a, a);
            fma2(acc[i][0], aa, bb.x);
            fma2(acc[i][1], aa, bb.y);
        }
    }
    const float scale = 0.17677669529663687f;  // 1/sqrt(32)
#pragma unroll
    for (int i = 0; i < 4; i++) {
        int row = m0 + ty * 4 + i;
#pragma unroll
        for (int j = 0; j < 2; j++) {
            float2 v = unpack2(acc[i][j]);
            int col = n0 + tx * 4 + j * 2;
            g_S[((size_t)bh * Lc + row) * Lc + col]     = v.x * scale + g_bias[(size_t)(b * Lc + row) * Lc + col];
            g_S[((size_t)bh * Lc + row) * Lc + col + 1] = v.y * scale + g_bias[(size_t)(b * Lc + row) * Lc + col + 1];
        }
    }
}

// ---------------- row softmax with key mask ----------------
__global__ void softmax_kernel(const float* __restrict__ mask) {
    __shared__ float sh[8];
    int r = blockIdx.x;         // 0 .. B*H*L-1
    int t = threadIdx.x;
    int b = r >> 13;            // r / (H*L)
    float* S = g_S + (size_t)r * Lc;
    float vals[4];
    float mx = -3.0e38f;
#pragma unroll
    for (int i = 0; i < 4; i++) {
        int c = t + i * 256;
        float s = S[c];
        if (mask[b * Lc + c] <= 0.f) s = -1e9f;
        vals[i] = s;
        mx = fmaxf(mx, s);
    }
    float gmx = blockMax(mx, sh);
    float sum = 0.f;
#pragma unroll
    for (int i = 0; i < 4; i++) {
        vals[i] = __expf(vals[i] - gmx);
        sum += vals[i];
    }
    float gs = blockSum(sum, sh);
    float inv = 1.f / gs;
#pragma unroll
    for (int i = 0; i < 4; i++) S[t + i * 256] = vals[i] * inv;
}

// ---------------- ctx = attn @ v, written in (B,L,D) layout (f32x2) ----------------
__global__ void ctx_kernel() {
    __shared__ float Ssh[64][65];
    __shared__ float Vs[64][36];
    int t = threadIdx.x;
    int m0 = blockIdx.x * 64;
    int bh = blockIdx.y; int b = bh >> 3, h = bh & 7;
    int row = t >> 2, sub = t & 3;
    u64 acc[4] = {};
    for (int k0 = 0; k0 < Lc; k0 += 64) {
#pragma unroll
        for (int i = 0; i < 16; i++) {
            int e = t + i * 256; int r = e >> 6, c = e & 63;
            Ssh[r][c] = g_S[((size_t)bh * Lc + m0 + r) * Lc + k0 + c];
        }
#pragma unroll
        for (int i = 0; i < 8; i++) {
            int e = t + i * 256; int kk = e >> 5, c = e & 31;
            Vs[kk][c] = g_v[(size_t)(b * Lc + k0 + kk) * Dc + h * DKc + c];
        }
        __syncthreads();
#pragma unroll 4
        for (int kk = 0; kk < 64; kk++) {
            float a = Ssh[row][kk];
            u64 aa = pack2(a, a);
            ulonglong2 v0 = *reinterpret_cast<const ulonglong2*>(&Vs[kk][sub * 8]);
            ulonglong2 v1 = *reinterpret_cast<const ulonglong2*>(&Vs[kk][sub * 8 + 4]);
            fma2(acc[0], aa, v0.x);
            fma2(acc[1], aa, v0.y);
            fma2(acc[2], aa, v1.x);
            fma2(acc[3], aa, v1.y);
        }
        __syncthreads();
    }
#pragma unroll
    for (int j = 0; j < 4; j++) {
        float2 v = unpack2(acc[j]);
        size_t base = (size_t)(b * Lc + m0 + row) * Dc + h * DKc + sub * 8 + j * 2;
        g_ctx[base] = v.x;
        g_ctx[base + 1] = v.y;
    }
}

// ---------------- LN1: h_V_new = LN(h_V + ctx@Wo+bo) * mask ----------------
__global__ void ln1_kernel(const float* __restrict__ hV,
                           const float* __restrict__ gvec, const float* __restrict__ bvec,
                           const float* __restrict__ mask, float* __restrict__ out) {
    __shared__ float sh[8];
    int row = blockIdx.x, t = threadIdx.x;
    float x = hV[row * Dc + t] + g_tmp[row * Dc + t];
    float mean = blockSum(x, sh) * (1.f / Dc);
    float d = x - mean;
    float var = blockSum(d * d, sh) * (1.f / Dc);
    float y = d * rsqrtf(var + 1e-5f) * gvec[t] + bvec[t];
    out[row * Dc + t] = y * mask[row];
}

// ---------- MLP layer 1 fused: gather + 128-tile GEMM(Kd=512) + hvp + gelu ----------
__global__ void __launch_bounds__(256, 2)
layer1_128(const float* __restrict__ Ein,
           const int* __restrict__ E_idx,
           const float* __restrict__ hVnew,
           const float* __restrict__ W11) {
    __shared__ float As[16][132];
    __shared__ float Bs[16][128];
    __shared__ int nbb[128];
    int t = threadIdx.x;
    int tx = t & 15, ty = t >> 4;
    int m0 = blockIdx.y * 128, n0 = blockIdx.x * 128;
    if (t < 128) {
        int r = m0 + t;
        int b_ = r / (Lc * Kc);
        nbb[t] = (b_ * Lc + E_idx[r]) * Dc;
    }
    __syncthreads();
    const float* Bblk = W11 + (size_t)256 * Dc + n0;
    u64 acc[8][4] = {};
    for (int k0 = 0; k0 < 512; k0 += 16) {
        float4 av[2], bv[2];
#pragma unroll
        for (int i = 0; i < 2; i++) {
            int f = t * 2 + i;
            int r = f >> 2, c4 = f & 3;
            int kc = k0 + c4 * 4;
            if (kc < 256)
                av[i] = *reinterpret_cast<const float4*>(Ein + (size_t)(m0 + r) * Dc + kc);
            else
                av[i] = *reinterpret_cast<const float4*>(hVnew + nbb[r] + kc - 256);
            int kk = f >> 5, c = (f & 31) * 4;
            bv[i] = *reinterpret_cast<const float4*>(Bblk + (size_t)(k0 + kk) * Dc + c);
        }
        __syncthreads();
#pragma unroll
        for (int i = 0; i < 2; i++) {
            int f = t * 2 + i;
            int r = f >> 2, c4 = (f & 3) * 4;
            As[c4 + 0][r] = av[i].x;
            As[c4 + 1][r] = av[i].y;
            As[c4 + 2][r] = av[i].z;
            As[c4 + 3][r] = av[i].w;
            int kk = f >> 5, c = (f & 31) * 4;
            *reinterpret_cast<float4*>(&Bs[kk][c]) = bv[i];
        }
        __syncthreads();
#pragma unroll
        for (int kk = 0; kk < 16; kk++) {
            float4 a0 = *reinterpret_cast<const float4*>(&As[kk][ty * 8]);
            float4 a1 = *reinterpret_cast<const float4*>(&As[kk][ty * 8 + 4]);
            ulonglong2 b0 = *reinterpret_cast<const ulonglong2*>(&Bs[kk][tx * 8]);
            ulonglong2 b1 = *reinterpret_cast<const ulonglong2*>(&Bs[kk][tx * 8 + 4]);
            float a[8] = {a0.x, a0.y, a0.z, a0.w, a1.x, a1.y, a1.z, a1.w};
#pragma unroll
            for (int i = 0; i < 8; i++) {
                u64 aa = pack2(a[i], a[i]);
                fma2(acc[i][0], aa, b0.x);
                fma2(acc[i][1], aa, b0.y);
                fma2(acc[i][2], aa, b1.x);
                fma2(acc[i][3], aa, b1.y);
            }
        }
    }
#pragma unroll
    for (int i = 0; i < 8; i++) {
        int row = m0 + ty * 8 + i;
        int hv = (row / Kc) * Dc;
        int col = n0 + tx * 8;
        float o[8];
#pragma unroll
        for (int j = 0; j < 4; j++) {
            float2 v = unpack2(acc[i][j]);
            o[j * 2] = v.x; o[j * 2 + 1] = v.y;
        }
#pragma unroll
        for (int j = 0; j < 8; j++)
            o[j] = gelu_exact(o[j] + g_hvp[hv + col + j]);
        float4* cp = reinterpret_cast<float4*>(g_m1 + (size_t)row * Dc + col);
        cp[0] = make_float4(o[0], o[1], o[2], o[3]);
        cp[1] = make_float4(o[4], o[5], o[6], o[7]);
    }
}

// ---------------- LN2: h_E = LN(E + msg) ----------------
__global__ void ln2_kernel(const float* __restrict__ Ein,
                           const float* __restrict__ gvec, const float* __restrict__ bvec,
                           float* __restrict__ out) {
    __shared__ float sh[8];
    int row = blockIdx.x, t = threadIdx.x;
    float x = Ein[(size_t)row * Dc + t] + g_m1[(size_t)row * Dc + t];
    float mean = blockSum(x, sh) * (1.f / Dc);
    float d = x - mean;
    float var = blockSum(d * d, sh) * (1.f / Dc);
    out[(size_t)row * Dc + t] = d * rsqrtf(var + 1e-5f) * gvec[t] + bvec[t];
}

// ---------------- host launch ----------------
extern "C" void kernel_launch(void* const* d_in, const int* in_sizes, int n_in,
                              void* d_out, int out_size) {
    const float* h_V    = (const float*)d_in[0];
    const float* E      = (const float*)d_in[1];
    const int*   E_idx  = (const int*)  d_in[2];
    const float* mask   = (const float*)d_in[3];
    const float* nonE   = (const float*)d_in[4];
    const float* bias_W = (const float*)d_in[5];
    const float* bias_b = (const float*)d_in[6];
    const float* Wq = (const float*)d_in[7];  const float* bq = (const float*)d_in[8];
    const float* Wk = (const float*)d_in[9];  const float* bk = (const float*)d_in[10];
    const float* Wv = (const float*)d_in[11]; const float* bv = (const float*)d_in[12];
    const float* Wo = (const float*)d_in[13]; const float* bo = (const float*)d_in[14];
    const float* ln1g = (const float*)d_in[15]; const float* ln1b = (const float*)d_in[16];
    const float* W11 = (const float*)d_in[17]; const float* b11 = (const float*)d_in[18];
    const float* W12 = (const float*)d_in[19]; const float* b12 = (const float*)d_in[20];
    const float* W13 = (const float*)d_in[21]; const float* b13 = (const float*)d_in[22];
    const float* ln2g = (const float*)d_in[23]; const float* ln2b = (const float*)d_in[24];

    float* out_hV = (float*)d_out;
    float* out_hE = out_hV + M1c * Dc;

    float *p_q, *p_k, *p_v, *p_ctx, *p_tmp, *p_hvp, *p_m1, *p_m2;
    cudaGetSymbolAddress((void**)&p_q,   g_q);
    cudaGetSymbolAddress((void**)&p_k,   g_k);
    cudaGetSymbolAddress((void**)&p_v,   g_v);
    cudaGetSymbolAddress((void**)&p_ctx, g_ctx);
    cudaGetSymbolAddress((void**)&p_tmp, g_tmp);
    cudaGetSymbolAddress((void**)&p_hvp, g_hvp);
    cudaGetSymbolAddress((void**)&p_m1,  g_m1);
    cudaGetSymbolAddress((void**)&p_m2,  g_m2);

    // attention bias
    bias_base_kernel<<<1, 256>>>(nonE, bias_W, bias_b);
    bias_fill_kernel<<<(Bc * Lc * Lc) / 256, 256>>>();
    bias_scatter_kernel<<<(Bc * Lc) / 8, 256>>>(E, E_idx, bias_W, bias_b);

    // qkv
    dim3 gqkv(Dc / 64, M1c / 64);
    gemm64<<<gqkv, 256>>>(h_V, Wq, p_q, M1c, Dc, Dc, bq, 0);
    gemm64<<<gqkv, 256>>>(h_V, Wk, p_k, M1c, Dc, Dc, bk, 0);
    gemm64<<<gqkv, 256>>>(h_V, Wv, p_v, M1c, Dc, Dc, bv, 0);

    // attention
    logits_kernel<<<dim3(Lc / 64, Lc / 64, Bc * Hc), 256>>>();
    softmax_kernel<<<Bc * Hc * Lc, 256>>>(mask);
    ctx_kernel<<<dim3(Lc / 64, Bc * Hc), 256>>>();

    // out proj + LN1 (writes h_V_new into d_out)
    gemm64<<<gqkv, 256>>>(p_ctx, Wo, p_tmp, M1c, Dc, Dc, bo, 0);
    ln1_kernel<<<M1c, 256>>>(h_V, ln1g, ln1b, mask, out_hV);

    // MLP
    gemm64<<<gqkv, 256>>>(out_hV, W11, p_hvp, M1c, Dc, Dc, b11, 0);
    dim3 gbig(Dc / 128, M2c / 128);
    layer1_128<<<gbig, 256>>>(E, E_idx, out_hV, W11);
    gemm128<<<gbig, 256>>>(p_m1, W12, p_m2, M2c, Dc, Dc, b12, 1);
    gemm128<<<gbig, 256>>>(p_m2, W13, p_m1, M2c, Dc, Dc, b13, 0);
    ln2_kernel<<<M2c, 256>>>(E, ln2g, ln2b, out_hE);
}

// round 5
// speedup vs baseline: 1.2058x; 1.2058x over previous
#include <cuda_runtime.h>
#include <math.h>
#include <mma.h>

using namespace nvcuda;

#define Bc 4
#define Lc 1024
#define Kc 30
#define Dc 256
#define Hc 8
#define DKc 32

#define M1c (Bc*Lc)          // 4096
#define M2c (Bc*Lc*Kc)       // 122880

// ---------------- scratch (static device globals; no allocations) ----------------
__device__ float g_q[M1c*Dc];
__device__ float g_k[M1c*Dc];
__device__ float g_v[M1c*Dc];
__device__ float g_bias[Bc*Lc*Lc];              // 16 MB
__device__ float g_S[Bc*Hc*Lc*Lc];              // 128 MB attention logits/probs
__device__ float g_ctx[M1c*Dc];
__device__ float g_tmp[M1c*Dc];
__device__ float g_hvp[M1c*Dc];                 // h_V_new @ W11[0:256] + b11
__device__ float g_m1[M2c*Dc];                  // 126 MB
__device__ float g_m2[M2c*Dc];                  // 126 MB
__device__ float g_base;

// ---------------- packed f32x2 helpers ----------------
typedef unsigned long long u64;

__device__ __forceinline__ u64 pack2(float x, float y) {
    u64 r;
    asm("mov.b64 %0, {%1, %2};" : "=l"(r) : "f"(x), "f"(y));
    return r;
}
__device__ __forceinline__ void fma2(u64& d, u64 a, u64 b) {
    asm("fma.rn.f32x2 %0, %1, %2, %0;" : "+l"(d) : "l"(a), "l"(b));
}
__device__ __forceinline__ float2 unpack2(u64 v) {
    float2 f;
    asm("mov.b64 {%0, %1}, %2;" : "=f"(f.x), "=f"(f.y) : "l"(v));
    return f;
}
__device__ __forceinline__ float to_tf32(float x) {
    float y;
    asm("cvt.rna.tf32.f32 %0, %1;" : "=f"(y) : "f"(x));
    return y;
}

// ---------------- reduction helpers ----------------
__device__ __forceinline__ float blockSum(float v, float* sh) {
    int lane = threadIdx.x & 31, wid = threadIdx.x >> 5;
#pragma unroll
    for (int o = 16; o; o >>= 1) v += __shfl_down_sync(0xffffffffu, v, o);
    if (lane == 0) sh[wid] = v;
    __syncthreads();
    if (wid == 0) {
        float r = (lane < 8) ? sh[lane] : 0.f;
#pragma unroll
        for (int o = 4; o; o >>= 1) r += __shfl_down_sync(0xffffffffu, r, o);
        if (lane == 0) sh[0] = r;
    }
    __syncthreads();
    float out = sh[0];
    __syncthreads();
    return out;
}

__device__ __forceinline__ float blockMax(float v, float* sh) {
    int lane = threadIdx.x & 31, wid = threadIdx.x >> 5;
#pragma unroll
    for (int o = 16; o; o >>= 1) v = fmaxf(v, __shfl_down_sync(0xffffffffu, v, o));
    if (lane == 0) sh[wid] = v;
    __syncthreads();
    if (wid == 0) {
        float r = (lane < 8) ? sh[lane] : -3.0e38f;
#pragma unroll
        for (int o = 4; o; o >>= 1) r = fmaxf(r, __shfl_down_sync(0xffffffffu, r, o));
        if (lane == 0) sh[0] = r;
    }
    __syncthreads();
    float out = sh[0];
    __syncthreads();
    return out;
}

__device__ __forceinline__ float gelu_exact(float x) {
    return 0.5f * x * (1.0f + erff(x * 0.70710678118654752f));
}

// ---------------- bias base / fill / scatter ----------------
__global__ void bias_base_kernel(const float* __restrict__ nonE,
                                 const float* __restrict__ bias_W,
                                 const float* __restrict__ bias_b) {
    __shared__ float sh[8];
    int t = threadIdx.x;
    float p = nonE[t] * bias_W[t];
    float s = blockSum(p, sh);
    if (t == 0) g_base = s + bias_b[0];
}

__global__ void bias_fill_kernel() {
    int i = blockIdx.x * 256 + threadIdx.x;
    g_bias[i] = g_base;
}

// one warp per (b,l); k loop serial on lane 0 => last write wins for duplicate idx
__global__ void bias_scatter_kernel(const float* __restrict__ E,
                                    const int* __restrict__ E_idx,
                                    const float* __restrict__ bias_W,
                                    const float* __restrict__ bias_b) {
    int w = (blockIdx.x * blockDim.x + threadIdx.x) >> 5;
    int lane = threadIdx.x & 31;
    if (w >= Bc * Lc) return;
    float bb = bias_b[0];
    for (int k = 0; k < Kc; k++) {
        const float* er = E + (w * Kc + k) * Dc;
        float p = 0.f;
#pragma unroll
        for (int c = lane; c < Dc; c += 32) p += er[c] * bias_W[c];
#pragma unroll
        for (int o = 16; o; o >>= 1) p += __shfl_down_sync(0xffffffffu, p, o);
        if (lane == 0) {
            int idx = E_idx[w * Kc + k];
            g_bias[w * Lc + idx] = p + bb;
        }
    }
}

// ---------------- 64x64 tiled fp32 GEMM with f32x2 (small M GEMMs) ----------------
__global__ void gemm64(const float* __restrict__ A, const float* __restrict__ Bm,
                       float* __restrict__ C, int M, int N, int Kd,
                       const float* __restrict__ bias, int act) {
    __shared__ float As[64][17];
    __shared__ float Bs[16][64];
    int t = threadIdx.x;
    int tx = t & 15, ty = t >> 4;
    int m0 = blockIdx.y * 64, n0 = blockIdx.x * 64;
    u64 acc[4][2] = {};
    for (int k0 = 0; k0 < Kd; k0 += 16) {
#pragma unroll
        for (int i = 0; i < 4; i++) {
            int e = t + i * 256; int r = e >> 4, c = e & 15;
            As[r][c] = A[(size_t)(m0 + r) * Kd + k0 + c];
        }
#pragma unroll
        for (int i = 0; i < 4; i++) {
            int e = t + i * 256; int kk = e >> 6, c = e & 63;
            Bs[kk][c] = Bm[(size_t)(k0 + kk) * N + n0 + c];
        }
        __syncthreads();
#pragma unroll
        for (int kk = 0; kk < 16; kk++) {
            ulonglong2 bb = *reinterpret_cast<const ulonglong2*>(&Bs[kk][tx * 4]);
#pragma unroll
            for (int i = 0; i < 4; i++) {
                float a = As[ty * 4 + i][kk];
                u64 aa = pack2(a, a);
                fma2(acc[i][0], aa, bb.x);
                fma2(acc[i][1], aa, bb.y);
            }
        }
        __syncthreads();
    }
#pragma unroll
    for (int i = 0; i < 4; i++) {
        int row = m0 + ty * 4 + i;
#pragma unroll
        for (int j = 0; j < 2; j++) {
            float2 v = unpack2(acc[i][j]);
            int col = n0 + tx * 4 + j * 2;
            float x0 = v.x + (bias ? bias[col] : 0.f);
            float x1 = v.y + (bias ? bias[col + 1] : 0.f);
            if (act == 1) { x0 = gelu_exact(x0); x1 = gelu_exact(x1); }
            C[(size_t)row * N + col] = x0;
            C[(size_t)row * N + col + 1] = x1;
        }
    }
}

// ============== tensor-core tf32 128x128 GEMM, raw-accumulator store ==============
// MODE 1: A_eff = gelu(Araw + aux[hvb[row] + k])  (hvp fused, per-row base)
// MODE 2: A_eff = gelu(Araw + aux[k])             (b12 fused)
// Stores raw acc (no bias/act) to C.
template<int MODE>
__global__ void __launch_bounds__(256, 2)
gemm_tc(const float* __restrict__ A, const float* __restrict__ Bm,
        float* __restrict__ C, int M, int N, int Kd,
        const float* __restrict__ aux) {
    __shared__ float As[128][24];
    __shared__ float Bs[16][136];
    __shared__ int hvb[128];
    int t = threadIdx.x;
    int wid = t >> 5;
    int wm = wid & 3, wn = wid >> 2;
    int m0 = blockIdx.y * 128, n0 = blockIdx.x * 128;
    if (MODE == 1 && t < 128) hvb[t] = ((m0 + t) / Kc) * Dc;
    if (MODE == 1) __syncthreads();

    const float* Ablk = A + (size_t)m0 * Kd;
    const float* Bblk = Bm + n0;

    wmma::fragment<wmma::accumulator, 16, 16, 8, float> acc[2][4];
#pragma unroll
    for (int i = 0; i < 2; i++)
#pragma unroll
        for (int j = 0; j < 4; j++) wmma::fill_fragment(acc[i][j], 0.f);

    for (int k0 = 0; k0 < Kd; k0 += 16) {
        float4 av[2], bv[2];
#pragma unroll
        for (int i = 0; i < 2; i++) {
            int f = t * 2 + i;                 // 0..511
            int r = f >> 2, c4 = f & 3;
            av[i] = *reinterpret_cast<const float4*>(Ablk + (size_t)r * Kd + k0 + c4 * 4);
            int kk = f >> 5, c = (f & 31) * 4;
            bv[i] = *reinterpret_cast<const float4*>(Bblk + (size_t)(k0 + kk) * N + c);
        }
        __syncthreads();
#pragma unroll
        for (int i = 0; i < 2; i++) {
            int f = t * 2 + i;
            int r = f >> 2, c4 = (f & 3) * 4;
            float vv[4] = {av[i].x, av[i].y, av[i].z, av[i].w};
#pragma unroll
            for (int j = 0; j < 4; j++) {
                int kc = k0 + c4 + j;
                float x = vv[j];
                if (MODE == 1) x = gelu_exact(x + aux[hvb[r] + kc]);
                if (MODE == 2) x = gelu_exact(x + aux[kc]);
                As[r][c4 + j] = to_tf32(x);
            }
            int kk = f >> 5, c = (f & 31) * 4;
            Bs[kk][c + 0] = to_tf32(bv[i].x);
            Bs[kk][c + 1] = to_tf32(bv[i].y);
            Bs[kk][c + 2] = to_tf32(bv[i].z);
            Bs[kk][c + 3] = to_tf32(bv[i].w);
        }
        __syncthreads();
#pragma unroll
        for (int k8 = 0; k8 < 16; k8 += 8) {
            wmma::fragment<wmma::matrix_a, 16, 16, 8, wmma::precision::tf32, wmma::row_major> af[2];
            wmma::load_matrix_sync(af[0], &As[wm * 32][k8], 24);
            wmma::load_matrix_sync(af[1], &As[wm * 32 + 16][k8], 24);
#pragma unroll
            for (int ni = 0; ni < 4; ni++) {
                wmma::fragment<wmma::matrix_b, 16, 16, 8, wmma::precision::tf32, wmma::row_major> bf;
                wmma::load_matrix_sync(bf, &Bs[k8][wn * 64 + ni * 16], 136);
                wmma::mma_sync(acc[0][ni], af[0], bf, acc[0][ni]);
                wmma::mma_sync(acc[1][ni], af[1], bf, acc[1][ni]);
            }
        }
    }
#pragma unroll
    for (int mi = 0; mi < 2; mi++)
#pragma unroll
        for (int ni = 0; ni < 4; ni++) {
            float* cp = C + (size_t)(m0 + wm * 32 + mi * 16) * N + n0 + wn * 64 + ni * 16;
            wmma::store_matrix_sync(cp, acc[mi][ni], N, wmma::mem_row_major);
        }
}

// ---- layer1: gather + tf32 TC GEMM, Kd=512 over [E | h_V_new[E_idx]], raw store ----
__global__ void __launch_bounds__(256, 2)
layer1_tc(const float* __restrict__ Ein,
          const int* __restrict__ E_idx,
          const float* __restrict__ hVnew,
          const float* __restrict__ W11) {
    __shared__ float As[128][24];
    __shared__ float Bs[16][136];
    __shared__ int nbb[128];
    int t = threadIdx.x;
    int wid = t >> 5;
    int wm = wid & 3, wn = wid >> 2;
    int m0 = blockIdx.y * 128, n0 = blockIdx.x * 128;
    if (t < 128) {
        int r = m0 + t;
        int b_ = r / (Lc * Kc);
        nbb[t] = (b_ * Lc + E_idx[r]) * Dc;
    }
    __syncthreads();
    const float* Bblk = W11 + (size_t)256 * Dc + n0;

    wmma::fragment<wmma::accumulator, 16, 16, 8, float> acc[2][4];
#pragma unroll
    for (int i = 0; i < 2; i++)
#pragma unroll
        for (int j = 0; j < 4; j++) wmma::fill_fragment(acc[i][j], 0.f);

    for (int k0 = 0; k0 < 512; k0 += 16) {
        float4 av[2], bv[2];
#pragma unroll
        for (int i = 0; i < 2; i++) {
            int f = t * 2 + i;
            int r = f >> 2, c4 = f & 3;
            int kc = k0 + c4 * 4;
            if (kc < 256)
                av[i] = *reinterpret_cast<const float4*>(Ein + (size_t)(m0 + r) * Dc + kc);
            else
                av[i] = *reinterpret_cast<const float4*>(hVnew + nbb[r] + kc - 256);
            int kk = f >> 5, c = (f & 31) * 4;
            bv[i] = *reinterpret_cast<const float4*>(Bblk + (size_t)(k0 + kk) * Dc + c);
        }
        __syncthreads();
#pragma unroll
        for (int i = 0; i < 2; i++) {
            int f = t * 2 + i;
            int r = f >> 2, c4 = (f & 3) * 4;
            As[r][c4 + 0] = to_tf32(av[i].x);
            As[r][c4 + 1] = to_tf32(av[i].y);
            As[r][c4 + 2] = to_tf32(av[i].z);
            As[r][c4 + 3] = to_tf32(av[i].w);
            int kk = f >> 5, c = (f & 31) * 4;
            Bs[kk][c + 0] = to_tf32(bv[i].x);
            Bs[kk][c + 1] = to_tf32(bv[i].y);
            Bs[kk][c + 2] = to_tf32(bv[i].z);
            Bs[kk][c + 3] = to_tf32(bv[i].w);
        }
        __syncthreads();
#pragma unroll
        for (int k8 = 0; k8 < 16; k8 += 8) {
            wmma::fragment<wmma::matrix_a, 16, 16, 8, wmma::precision::tf32, wmma::row_major> af[2];
            wmma::load_matrix_sync(af[0], &As[wm * 32][k8], 24);
            wmma::load_matrix_sync(af[1], &As[wm * 32 + 16][k8], 24);
#pragma unroll
            for (int ni = 0; ni < 4; ni++) {
                wmma::fragment<wmma::matrix_b, 16, 16, 8, wmma::precision::tf32, wmma::row_major> bf;
                wmma::load_matrix_sync(bf, &Bs[k8][wn * 64 + ni * 16], 136);
                wmma::mma_sync(acc[0][ni], af[0], bf, acc[0][ni]);
                wmma::mma_sync(acc[1][ni], af[1], bf, acc[1][ni]);
            }
        }
    }
#pragma unroll
    for (int mi = 0; mi < 2; mi++)
#pragma unroll
        for (int ni = 0; ni < 4; ni++) {
            float* cp = g_m1 + (size_t)(m0 + wm * 32 + mi * 16) * Dc + n0 + wn * 64 + ni * 16;
            wmma::store_matrix_sync(cp, acc[mi][ni], Dc, wmma::mem_row_major);
        }
}

// ---------------- logits: per (b,h) q@k^T * scale + bias (f32x2) ----------------
__global__ void logits_kernel() {
    __shared__ float As[64][33];
    __shared__ float Bs[32][68];
    int t = threadIdx.x;
    int tx = t & 15, ty = t >> 4;
    int n0 = blockIdx.x * 64, m0 = blockIdx.y * 64;
    int bh = blockIdx.z; int b = bh >> 3, h = bh & 7;
    const float* qb = g_q + (b * Lc) * Dc + h * DKc;
    const float* kb = g_k + (b * Lc) * Dc + h * DKc;
#pragma unroll
    for (int i = 0; i < 8; i++) {
        int e = t + i * 256; int r = e >> 5, c = e & 31;
        As[r][c] = qb[(size_t)(m0 + r) * Dc + c];
    }
#pragma unroll
    for (int i = 0; i < 8; i++) {
        int e = t + i * 256; int n = e >> 5, c = e & 31;
        Bs[c][n] = kb[(size_t)(n0 + n) * Dc + c];
    }
    __syncthreads();
    u64 acc[4][2] = {};
#pragma unroll
    for (int kk = 0; kk < 32; kk++) {
        ulonglong2 bb = *reinterpret_cast<const ulonglong2*>(&Bs[kk][tx * 4]);
#pragma unroll
        for (int i = 0; i < 4; i++) {
            float a = As[ty * 4 + i][kk];
            u64 aa = pack2(a, a);
            fma2(acc[i][0], aa, bb.x);
            fma2(acc[i][1], aa, bb.y);
        }
    }
    const float scale = 0.17677669529663687f;  // 1/sqrt(32)
#pragma unroll
    for (int i = 0; i < 4; i++) {
        int row = m0 + ty * 4 + i;
#pragma unroll
        for (int j = 0; j < 2; j++) {
            float2 v = unpack2(acc[i][j]);
            int col = n0 + tx * 4 + j * 2;
            g_S[((size_t)bh * Lc + row) * Lc + col]     = v.x * scale + g_bias[(size_t)(b * Lc + row) * Lc + col];
            g_S[((size_t)bh * Lc + row) * Lc + col + 1] = v.y * scale + g_bias[(size_t)(b * Lc + row) * Lc + col + 1];
        }
    }
}

// ---------------- row softmax with key mask ----------------
__global__ void softmax_kernel(const float* __restrict__ mask) {
    __shared__ float sh[8];
    int r = blockIdx.x;         // 0 .. B*H*L-1
    int t = threadIdx.x;
    int b = r >> 13;            // r / (H*L)
    float* S = g_S + (size_t)r * Lc;
    float vals[4];
    float mx = -3.0e38f;
#pragma unroll
    for (int i = 0; i < 4; i++) {
        int c = t + i * 256;
        float s = S[c];
        if (mask[b * Lc + c] <= 0.f) s = -1e9f;
        vals[i] = s;
        mx = fmaxf(mx, s);
    }
    float gmx = blockMax(mx, sh);
    float sum = 0.f;
#pragma unroll
    for (int i = 0; i < 4; i++) {
        vals[i] = __expf(vals[i] - gmx);
        sum += vals[i];
    }
    float gs = blockSum(sum, sh);
    float inv = 1.f / gs;
#pragma unroll
    for (int i = 0; i < 4; i++) S[t + i * 256] = vals[i] * inv;
}

// ---------------- ctx = attn @ v, written in (B,L,D) layout (f32x2) ----------------
__global__ void ctx_kernel() {
    __shared__ float Ssh[64][65];
    __shared__ float Vs[64][36];
    int t = threadIdx.x;
    int m0 = blockIdx.x * 64;
    int bh = blockIdx.y; int b = bh >> 3, h = bh & 7;
    int row = t >> 2, sub = t & 3;
    u64 acc[4] = {};
    for (int k0 = 0; k0 < Lc; k0 += 64) {
#pragma unroll
        for (int i = 0; i < 16; i++) {
            int e = t + i * 256; int r = e >> 6, c = e & 63;
            Ssh[r][c] = g_S[((size_t)bh * Lc + m0 + r) * Lc + k0 + c];
        }
#pragma unroll
        for (int i = 0; i < 8; i++) {
            int e = t + i * 256; int kk = e >> 5, c = e & 31;
            Vs[kk][c] = g_v[(size_t)(b * Lc + k0 + kk) * Dc + h * DKc + c];
        }
        __syncthreads();
#pragma unroll 4
        for (int kk = 0; kk < 64; kk++) {
            float a = Ssh[row][kk];
            u64 aa = pack2(a, a);
            ulonglong2 v0 = *reinterpret_cast<const ulonglong2*>(&Vs[kk][sub * 8]);
            ulonglong2 v1 = *reinterpret_cast<const ulonglong2*>(&Vs[kk][sub * 8 + 4]);
            fma2(acc[0], aa, v0.x);
            fma2(acc[1], aa, v0.y);
            fma2(acc[2], aa, v1.x);
            fma2(acc[3], aa, v1.y);
        }
        __syncthreads();
    }
#pragma unroll
    for (int j = 0; j < 4; j++) {
        float2 v = unpack2(acc[j]);
        size_t base = (size_t)(b * Lc + m0 + row) * Dc + h * DKc + sub * 8 + j * 2;
        g_ctx[base] = v.x;
        g_ctx[base + 1] = v.y;
    }
}

// ---------------- LN1: h_V_new = LN(h_V + ctx@Wo+bo) * mask ----------------
__global__ void ln1_kernel(const float* __restrict__ hV,
                           const float* __restrict__ gvec, const float* __restrict__ bvec,
                           const float* __restrict__ mask, float* __restrict__ out) {
    __shared__ float sh[8];
    int row = blockIdx.x, t = threadIdx.x;
    float x = hV[row * Dc + t] + g_tmp[row * Dc + t];
    float mean = blockSum(x, sh) * (1.f / Dc);
    float d = x - mean;
    float var = blockSum(d * d, sh) * (1.f / Dc);
    float y = d * rsqrtf(var + 1e-5f) * gvec[t] + bvec[t];
    out[row * Dc + t] = y * mask[row];
}

// ---------------- LN2: h_E = LN(E + m1_raw + b13) ----------------
__global__ void ln2_kernel(const float* __restrict__ Ein,
                           const float* __restrict__ b13,
                           const float* __restrict__ gvec, const float* __restrict__ bvec,
                           float* __restrict__ out) {
    __shared__ float sh[8];
    int row = blockIdx.x, t = threadIdx.x;
    float x = Ein[(size_t)row * Dc + t] + g_m1[(size_t)row * Dc + t] + b13[t];
    float mean = blockSum(x, sh) * (1.f / Dc);
    float d = x - mean;
    float var = blockSum(d * d, sh) * (1.f / Dc);
    out[(size_t)row * Dc + t] = d * rsqrtf(var + 1e-5f) * gvec[t] + bvec[t];
}

// ---------------- host launch ----------------
extern "C" void kernel_launch(void* const* d_in, const int* in_sizes, int n_in,
                              void* d_out, int out_size) {
    const float* h_V    = (const float*)d_in[0];
    const float* E      = (const float*)d_in[1];
    const int*   E_idx  = (const int*)  d_in[2];
    const float* mask   = (const float*)d_in[3];
    const float* nonE   = (const float*)d_in[4];
    const float* bias_W = (const float*)d_in[5];
    const float* bias_b = (const float*)d_in[6];
    const float* Wq = (const float*)d_in[7];  const float* bq = (const float*)d_in[8];
    const float* Wk = (const float*)d_in[9];  const float* bk = (const float*)d_in[10];
    const float* Wv = (const float*)d_in[11]; const float* bv = (const float*)d_in[12];
    const float* Wo = (const float*)d_in[13]; const float* bo = (const float*)d_in[14];
    const float* ln1g = (const float*)d_in[15]; const float* ln1b = (const float*)d_in[16];
    const float* W11 = (const float*)d_in[17]; const float* b11 = (const float*)d_in[18];
    const float* W12 = (const float*)d_in[19]; const float* b12 = (const float*)d_in[20];
    const float* W13 = (const float*)d_in[21]; const float* b13 = (const float*)d_in[22];
    const float* ln2g = (const float*)d_in[23]; const float* ln2b = (const float*)d_in[24];

    float* out_hV = (float*)d_out;
    float* out_hE = out_hV + M1c * Dc;

    float *p_q, *p_k, *p_v, *p_ctx, *p_tmp, *p_hvp, *p_m1, *p_m2;
    cudaGetSymbolAddress((void**)&p_q,   g_q);
    cudaGetSymbolAddress((void**)&p_k,   g_k);
    cudaGetSymbolAddress((void**)&p_v,   g_v);
    cudaGetSymbolAddress((void**)&p_ctx, g_ctx);
    cudaGetSymbolAddress((void**)&p_tmp, g_tmp);
    cudaGetSymbolAddress((void**)&p_hvp, g_hvp);
    cudaGetSymbolAddress((void**)&p_m1,  g_m1);
    cudaGetSymbolAddress((void**)&p_m2,  g_m2);

    // attention bias
    bias_base_kernel<<<1, 256>>>(nonE, bias_W, bias_b);
    bias_fill_kernel<<<(Bc * Lc * Lc) / 256, 256>>>();
    bias_scatter_kernel<<<(Bc * Lc) / 8, 256>>>(E, E_idx, bias_W, bias_b);

    // qkv
    dim3 gqkv(Dc / 64, M1c / 64);
    gemm64<<<gqkv, 256>>>(h_V, Wq, p_q, M1c, Dc, Dc, bq, 0);
    gemm64<<<gqkv, 256>>>(h_V, Wk, p_k, M1c, Dc, Dc, bk, 0);
    gemm64<<<gqkv, 256>>>(h_V, Wv, p_v, M1c, Dc, Dc, bv, 0);

    // attention
    logits_kernel<<<dim3(Lc / 64, Lc / 64, Bc * Hc), 256>>>();
    softmax_kernel<<<Bc * Hc * Lc, 256>>>(mask);
    ctx_kernel<<<dim3(Lc / 64, Bc * Hc), 256>>>();

    // out proj + LN1 (writes h_V_new into d_out)
    gemm64<<<gqkv, 256>>>(p_ctx, Wo, p_tmp, M1c, Dc, Dc, bo, 0);
    ln1_kernel<<<M1c, 256>>>(h_V, ln1g, ln1b, mask, out_hV);

    // MLP (tensor-core tf32, raw-acc stores, bias+gelu fused into next consumer's load)
    gemm64<<<gqkv, 256>>>(out_hV, W11, p_hvp, M1c, Dc, Dc, b11, 0);
    dim3 gbig(Dc / 128, M2c / 128);
    layer1_tc<<<gbig, 256>>>(E, E_idx, out_hV, W11);                 // m1 = raw
    gemm_tc<1><<<gbig, 256>>>(p_m1, W12, p_m2, M2c, Dc, Dc, p_hvp); // m2 = gelu(m1+hvp) @ W12 (raw)
    gemm_tc<2><<<gbig, 256>>>(p_m2, W13, p_m1, M2c, Dc, Dc, b12);   // m1 = gelu(m2+b12) @ W13 (raw)
    ln2_kernel<<<M2c, 256>>>(E, b13, ln2g, ln2b, out_hE);
}

// round 7
// speedup vs baseline: 1.3530x; 1.1221x over previous
#include <cuda_runtime.h>
#include <math.h>
#include <mma.h>

using namespace nvcuda;

#define Bc 4
#define Lc 1024
#define Kc 30
#define Dc 256
#define Hc 8
#define DKc 32

#define M1c (Bc*Lc)          // 4096
#define M2c (Bc*Lc*Kc)       // 122880

// ---------------- scratch (static device globals; no allocations) ----------------
__device__ float g_q[M1c*Dc];
__device__ float g_k[M1c*Dc];
__device__ float g_v[M1c*Dc];
__device__ float g_bias[Bc*Lc*Lc];              // 16 MB (fits in L2)
__device__ float g_ctx[M1c*Dc];
__device__ float g_tmp[M1c*Dc];
__device__ float g_hvp[M1c*Dc];                 // h_V_new @ W11[0:256] + b11
__device__ float g_m1[M2c*Dc];                  // 126 MB
__device__ float g_m2[M2c*Dc];                  // 126 MB
__device__ float g_base;

// ---------------- packed f32x2 helpers ----------------
typedef unsigned long long u64;

__device__ __forceinline__ u64 pack2(float x, float y) {
    u64 r;
    asm("mov.b64 %0, {%1, %2};" : "=l"(r) : "f"(x), "f"(y));
    return r;
}
__device__ __forceinline__ void fma2(u64& d, u64 a, u64 b) {
    asm("fma.rn.f32x2 %0, %1, %2, %0;" : "+l"(d) : "l"(a), "l"(b));
}
__device__ __forceinline__ float2 unpack2(u64 v) {
    float2 f;
    asm("mov.b64 {%0, %1}, %2;" : "=f"(f.x), "=f"(f.y) : "l"(v));
    return f;
}
__device__ __forceinline__ float to_tf32(float x) {
    float y;
    asm("cvt.rna.tf32.f32 %0, %1;" : "=f"(y) : "f"(x));
    return y;
}

// ---------------- reduction helpers ----------------
__device__ __forceinline__ float blockSum(float v, float* sh) {
    int lane = threadIdx.x & 31, wid = threadIdx.x >> 5;
#pragma unroll
    for (int o = 16; o; o >>= 1) v += __shfl_down_sync(0xffffffffu, v, o);
    if (lane == 0) sh[wid] = v;
    __syncthreads();
    if (wid == 0) {
        float r = (lane < 8) ? sh[lane] : 0.f;
#pragma unroll
        for (int o = 4; o; o >>= 1) r += __shfl_down_sync(0xffffffffu, r, o);
        if (lane == 0) sh[0] = r;
    }
    __syncthreads();
    float out = sh[0];
    __syncthreads();
    return out;
}

__device__ __forceinline__ float gelu_exact(float x) {
    return 0.5f * x * (1.0f + erff(x * 0.70710678118654752f));
}

// ---------------- bias base / fill / scatter ----------------
__global__ void bias_base_kernel(const float* __restrict__ nonE,
                                 const float* __restrict__ bias_W,
                                 const float* __restrict__ bias_b) {
    __shared__ float sh[8];
    int t = threadIdx.x;
    float p = nonE[t] * bias_W[t];
    float s = blockSum(p, sh);
    if (t == 0) g_base = s + bias_b[0];
}

__global__ void bias_fill_kernel() {
    int i = blockIdx.x * 256 + threadIdx.x;
    g_bias[i] = g_base;
}

// one warp per (b,l); k loop serial on lane 0 => last write wins for duplicate idx
__global__ void bias_scatter_kernel(const float* __restrict__ E,
                                    const int* __restrict__ E_idx,
                                    const float* __restrict__ bias_W,
                                    const float* __restrict__ bias_b) {
    int w = (blockIdx.x * blockDim.x + threadIdx.x) >> 5;
    int lane = threadIdx.x & 31;
    if (w >= Bc * Lc) return;
    float bb = bias_b[0];
    for (int k = 0; k < Kc; k++) {
        const float* er = E + (w * Kc + k) * Dc;
        float p = 0.f;
#pragma unroll
        for (int c = lane; c < Dc; c += 32) p += er[c] * bias_W[c];
#pragma unroll
        for (int o = 16; o; o >>= 1) p += __shfl_down_sync(0xffffffffu, p, o);
        if (lane == 0) {
            int idx = E_idx[w * Kc + k];
            g_bias[w * Lc + idx] = p + bb;
        }
    }
}

// ---------------- 64x64 tiled fp32 GEMM with f32x2 (small M GEMMs) ----------------
__global__ void gemm64(const float* __restrict__ A, const float* __restrict__ Bm,
                       float* __restrict__ C, int M, int N, int Kd,
                       const float* __restrict__ bias, int act) {
    __shared__ float As[64][17];
    __shared__ float Bs[16][64];
    int t = threadIdx.x;
    int tx = t & 15, ty = t >> 4;
    int m0 = blockIdx.y * 64, n0 = blockIdx.x * 64;
    u64 acc[4][2] = {};
    for (int k0 = 0; k0 < Kd; k0 += 16) {
#pragma unroll
        for (int i = 0; i < 4; i++) {
            int e = t + i * 256; int r = e >> 4, c = e & 15;
            As[r][c] = A[(size_t)(m0 + r) * Kd + k0 + c];
        }
#pragma unroll
        for (int i = 0; i < 4; i++) {
            int e = t + i * 256; int kk = e >> 6, c = e & 63;
            Bs[kk][c] = Bm[(size_t)(k0 + kk) * N + n0 + c];
        }
        __syncthreads();
#pragma unroll
        for (int kk = 0; kk < 16; kk++) {
            ulonglong2 bb = *reinterpret_cast<const ulonglong2*>(&Bs[kk][tx * 4]);
#pragma unroll
            for (int i = 0; i < 4; i++) {
                float a = As[ty * 4 + i][kk];
                u64 aa = pack2(a, a);
                fma2(acc[i][0], aa, bb.x);
                fma2(acc[i][1], aa, bb.y);
            }
        }
        __syncthreads();
    }
#pragma unroll
    for (int i = 0; i < 4; i++) {
        int row = m0 + ty * 4 + i;
#pragma unroll
        for (int j = 0; j < 2; j++) {
            float2 v = unpack2(acc[i][j]);
            int col = n0 + tx * 4 + j * 2;
            float x0 = v.x + (bias ? bias[col] : 0.f);
            float x1 = v.y + (bias ? bias[col + 1] : 0.f);
            if (act == 1) { x0 = gelu_exact(x0); x1 = gelu_exact(x1); }
            C[(size_t)row * N + col] = x0;
            C[(size_t)row * N + col + 1] = x1;
        }
    }
}

// ============== tensor-core tf32 128x128 GEMM, raw-accumulator store ==============
template<int MODE>
__global__ void __launch_bounds__(256, 2)
gemm_tc(const float* __restrict__ A, const float* __restrict__ Bm,
        float* __restrict__ C, int M, int N, int Kd,
        const float* __restrict__ aux) {
    __shared__ float As[128][24];
    __shared__ float Bs[16][136];
    __shared__ int hvb[128];
    int t = threadIdx.x;
    int wid = t >> 5;
    int wm = wid & 3, wn = wid >> 2;
    int m0 = blockIdx.y * 128, n0 = blockIdx.x * 128;
    if (MODE == 1 && t < 128) hvb[t] = ((m0 + t) / Kc) * Dc;
    if (MODE == 1) __syncthreads();

    const float* Ablk = A + (size_t)m0 * Kd;
    const float* Bblk = Bm + n0;

    wmma::fragment<wmma::accumulator, 16, 16, 8, float> acc[2][4];
#pragma unroll
    for (int i = 0; i < 2; i++)
#pragma unroll
        for (int j = 0; j < 4; j++) wmma::fill_fragment(acc[i][j], 0.f);

    for (int k0 = 0; k0 < Kd; k0 += 16) {
        float4 av[2], bv[2];
#pragma unroll
        for (int i = 0; i < 2; i++) {
            int f = t * 2 + i;                 // 0..511
            int r = f >> 2, c4 = f & 3;
            av[i] = *reinterpret_cast<const float4*>(Ablk + (size_t)r * Kd + k0 + c4 * 4);
            int kk = f >> 5, c = (f & 31) * 4;
            bv[i] = *reinterpret_cast<const float4*>(Bblk + (size_t)(k0 + kk) * N + c);
        }
        __syncthreads();
#pragma unroll
        for (int i = 0; i < 2; i++) {
            int f = t * 2 + i;
            int r = f >> 2, c4 = (f & 3) * 4;
            float vv[4] = {av[i].x, av[i].y, av[i].z, av[i].w};
#pragma unroll
            for (int j = 0; j < 4; j++) {
                int kc = k0 + c4 + j;
                float x = vv[j];
                if (MODE == 1) x = gelu_exact(x + aux[hvb[r] + kc]);
                if (MODE == 2) x = gelu_exact(x + aux[kc]);
                As[r][c4 + j] = to_tf32(x);
            }
            int kk = f >> 5, c = (f & 31) * 4;
            Bs[kk][c + 0] = to_tf32(bv[i].x);
            Bs[kk][c + 1] = to_tf32(bv[i].y);
            Bs[kk][c + 2] = to_tf32(bv[i].z);
            Bs[kk][c + 3] = to_tf32(bv[i].w);
        }
        __syncthreads();
#pragma unroll
        for (int k8 = 0; k8 < 16; k8 += 8) {
            wmma::fragment<wmma::matrix_a, 16, 16, 8, wmma::precision::tf32, wmma::row_major> af[2];
            wmma::load_matrix_sync(af[0], &As[wm * 32][k8], 24);
            wmma::load_matrix_sync(af[1], &As[wm * 32 + 16][k8], 24);
#pragma unroll
            for (int ni = 0; ni < 4; ni++) {
                wmma::fragment<wmma::matrix_b, 16, 16, 8, wmma::precision::tf32, wmma::row_major> bf;
                wmma::load_matrix_sync(bf, &Bs[k8][wn * 64 + ni * 16], 136);
                wmma::mma_sync(acc[0][ni], af[0], bf, acc[0][ni]);
                wmma::mma_sync(acc[1][ni], af[1], bf, acc[1][ni]);
            }
        }
    }
#pragma unroll
    for (int mi = 0; mi < 2; mi++)
#pragma unroll
        for (int ni = 0; ni < 4; ni++) {
            float* cp = C + (size_t)(m0 + wm * 32 + mi * 16) * N + n0 + wn * 64 + ni * 16;
            wmma::store_matrix_sync(cp, acc[mi][ni], N, wmma::mem_row_major);
        }
}

// ---- layer1: gather + tf32 TC GEMM, Kd=512 over [E | h_V_new[E_idx]], raw store ----
__global__ void __launch_bounds__(256, 2)
layer1_tc(const float* __restrict__ Ein,
          const int* __restrict__ E_idx,
          const float* __restrict__ hVnew,
          const float* __restrict__ W11) {
    __shared__ float As[128][24];
    __shared__ float Bs[16][136];
    __shared__ int nbb[128];
    int t = threadIdx.x;
    int wid = t >> 5;
    int wm = wid & 3, wn = wid >> 2;
    int m0 = blockIdx.y * 128, n0 = blockIdx.x * 128;
    if (t < 128) {
        int r = m0 + t;
        int b_ = r / (Lc * Kc);
        nbb[t] = (b_ * Lc + E_idx[r]) * Dc;
    }
    __syncthreads();
    const float* Bblk = W11 + (size_t)256 * Dc + n0;

    wmma::fragment<wmma::accumulator, 16, 16, 8, float> acc[2][4];
#pragma unroll
    for (int i = 0; i < 2; i++)
#pragma unroll
        for (int j = 0; j < 4; j++) wmma::fill_fragment(acc[i][j], 0.f);

    for (int k0 = 0; k0 < 512; k0 += 16) {
        float4 av[2], bv[2];
#pragma unroll
        for (int i = 0; i < 2; i++) {
            int f = t * 2 + i;
            int r = f >> 2, c4 = f & 3;
            int kc = k0 + c4 * 4;
            if (kc < 256)
                av[i] = *reinterpret_cast<const float4*>(Ein + (size_t)(m0 + r) * Dc + kc);
            else
                av[i] = *reinterpret_cast<const float4*>(hVnew + nbb[r] + kc - 256);
            int kk = f >> 5, c = (f & 31) * 4;
            bv[i] = *reinterpret_cast<const float4*>(Bblk + (size_t)(k0 + kk) * Dc + c);
        }
        __syncthreads();
#pragma unroll
        for (int i = 0; i < 2; i++) {
            int f = t * 2 + i;
            int r = f >> 2, c4 = (f & 3) * 4;
            As[r][c4 + 0] = to_tf32(av[i].x);
            As[r][c4 + 1] = to_tf32(av[i].y);
            As[r][c4 + 2] = to_tf32(av[i].z);
            As[r][c4 + 3] = to_tf32(av[i].w);
            int kk = f >> 5, c = (f & 31) * 4;
            Bs[kk][c + 0] = to_tf32(bv[i].x);
            Bs[kk][c + 1] = to_tf32(bv[i].y);
            Bs[kk][c + 2] = to_tf32(bv[i].z);
            Bs[kk][c + 3] = to_tf32(bv[i].w);
        }
        __syncthreads();
#pragma unroll
        for (int k8 = 0; k8 < 16; k8 += 8) {
            wmma::fragment<wmma::matrix_a, 16, 16, 8, wmma::precision::tf32, wmma::row_major> af[2];
            wmma::load_matrix_sync(af[0], &As[wm * 32][k8], 24);
            wmma::load_matrix_sync(af[1], &As[wm * 32 + 16][k8], 24);
#pragma unroll
            for (int ni = 0; ni < 4; ni++) {
                wmma::fragment<wmma::matrix_b, 16, 16, 8, wmma::precision::tf32, wmma::row_major> bf;
                wmma::load_matrix_sync(bf, &Bs[k8][wn * 64 + ni * 16], 136);
                wmma::mma_sync(acc[0][ni], af[0], bf, acc[0][ni]);
                wmma::mma_sync(acc[1][ni], af[1], bf, acc[1][ni]);
            }
        }
    }
#pragma unroll
    for (int mi = 0; mi < 2; mi++)
#pragma unroll
        for (int ni = 0; ni < 4; ni++) {
            float* cp = g_m1 + (size_t)(m0 + wm * 32 + mi * 16) * Dc + n0 + wn * 64 + ni * 16;
            wmma::store_matrix_sync(cp, acc[mi][ni], Dc, wmma::mem_row_major);
        }
}

// ================= fused flash attention (tf32 WMMA QK^T & PV, exact softmax) ========
// grid (16 m-tiles, 32 b*h), 128 threads. Two passes over K-tiles:
//   pass A: row max of (QK^T*scale + bias, masked)
//   pass B: P = exp(S - m), l += rowsum, O += P@V; epilogue O/l -> g_ctx
__global__ void __launch_bounds__(128)
flash_kernel(const float* __restrict__ mask) {
    __shared__ float Qs[64][36];
    __shared__ float Ks[64][36];
    __shared__ float Vs[64][36];
    __shared__ float Ss[64][68];
    __shared__ float rowm[64][2];
    __shared__ float rowl[64][2];
    __shared__ float maskS[64];

    int t = threadIdx.x;
    int wid = t >> 5;
    int m0 = blockIdx.x * 64;
    int bh = blockIdx.y; int b = bh >> 3, h = bh & 7;
    int bL = b * Lc;
    int myrow = t >> 1, myhalf = (t & 1) * 32;
    const float scale = 0.17677669529663687f;  // 1/sqrt(32)

    // load Q tile (pre-scaled, tf32)
#pragma unroll
    for (int f = t; f < 512; f += 128) {
        int r = f >> 3, c4 = (f & 7) * 4;
        float4 v = *reinterpret_cast<const float4*>(
            g_q + (size_t)(bL + m0 + r) * Dc + h * DKc + c4);
        Qs[r][c4 + 0] = to_tf32(v.x * scale);
        Qs[r][c4 + 1] = to_tf32(v.y * scale);
        Qs[r][c4 + 2] = to_tf32(v.z * scale);
        Qs[r][c4 + 3] = to_tf32(v.w * scale);
    }

    // ---------- pass A: row max ----------
    float mymax = -3.0e38f;
    for (int kt = 0; kt < 16; kt++) {
        int k0 = kt * 64;
#pragma unroll
        for (int f = t; f < 512; f += 128) {
            int r = f >> 3, c4 = (f & 7) * 4;
            float4 v = *reinterpret_cast<const float4*>(
                g_k + (size_t)(bL + k0 + r) * Dc + h * DKc + c4);
            Ks[r][c4 + 0] = to_tf32(v.x);
            Ks[r][c4 + 1] = to_tf32(v.y);
            Ks[r][c4 + 2] = to_tf32(v.z);
            Ks[r][c4 + 3] = to_tf32(v.w);
        }
        if (t < 64) maskS[t] = mask[bL + k0 + t];
        __syncthreads();

        wmma::fragment<wmma::accumulator, 16, 16, 8, float> sfr[4];
#pragma unroll
        for (int ni = 0; ni < 4; ni++) wmma::fill_fragment(sfr[ni], 0.f);
#pragma unroll
        for (int k8 = 0; k8 < 32; k8 += 8) {
            wmma::fragment<wmma::matrix_a, 16, 16, 8, wmma::precision::tf32, wmma::row_major> af;
            wmma::load_matrix_sync(af, &Qs[wid * 16][k8], 36);
#pragma unroll
            for (int ni = 0; ni < 4; ni++) {
                wmma::fragment<wmma::matrix_b, 16, 16, 8, wmma::precision::tf32, wmma::col_major> bf;
                wmma::load_matrix_sync(bf, &Ks[ni * 16][k8], 36);
                wmma::mma_sync(sfr[ni], af, bf, sfr[ni]);
            }
        }
#pragma unroll
        for (int ni = 0; ni < 4; ni++)
            wmma::store_matrix_sync(&Ss[wid * 16][ni * 16], sfr[ni], 68, wmma::mem_row_major);
        __syncthreads();

        const float* brow = g_bias + (size_t)(bL + m0 + myrow) * Lc + k0 + myhalf;
        const float* srow = &Ss[myrow][myhalf];
#pragma unroll
        for (int i = 0; i < 32; i += 4) {
            float4 bb = *reinterpret_cast<const float4*>(brow + i);
            float s0 = srow[i + 0] + bb.x; if (maskS[myhalf + i + 0] <= 0.f) s0 = -1e9f;
            float s1 = srow[i + 1] + bb.y; if (maskS[myhalf + i + 1] <= 0.f) s1 = -1e9f;
            float s2 = srow[i + 2] + bb.z; if (maskS[myhalf + i + 2] <= 0.f) s2 = -1e9f;
            float s3 = srow[i + 3] + bb.w; if (maskS[myhalf + i + 3] <= 0.f) s3 = -1e9f;
            mymax = fmaxf(mymax, fmaxf(fmaxf(s0, s1), fmaxf(s2, s3)));
        }
        __syncthreads();
    }
    rowm[myrow][t & 1] = mymax;
    __syncthreads();
    float m_final = fmaxf(rowm[myrow][0], rowm[myrow][1]);

    // ---------- pass B: exp + sum + PV ----------
    float myl = 0.f;
    wmma::fragment<wmma::accumulator, 16, 16, 8, float> ofr[2];
    wmma::fill_fragment(ofr[0], 0.f);
    wmma::fill_fragment(ofr[1], 0.f);

    for (int kt = 0; kt < 16; kt++) {
        int k0 = kt * 64;
#pragma unroll
        for (int f = t; f < 1024; f += 128) {
            int r = (f >> 3) & 63, c4 = (f & 7) * 4;
            const float* src = (f < 512) ? g_k : g_v;
            float4 v = *reinterpret_cast<const float4*>(
                src + (size_t)(bL + k0 + r) * Dc + h * DKc + c4);
            float* dst = (f < 512) ? &Ks[r][c4] : &Vs[r][c4];
            dst[0] = to_tf32(v.x);
            dst[1] = to_tf32(v.y);
            dst[2] = to_tf32(v.z);
            dst[3] = to_tf32(v.w);
        }
        if (t < 64) maskS[t] = mask[bL + k0 + t];
        __syncthreads();

        wmma::fragment<wmma::accumulator, 16, 16, 8, float> sfr[4];
#pragma unroll
        for (int ni = 0; ni < 4; ni++) wmma::fill_fragment(sfr[ni], 0.f);
#pragma unroll
        for (int k8 = 0; k8 < 32; k8 += 8) {
            wmma::fragment<wmma::matrix_a, 16, 16, 8, wmma::precision::tf32, wmma::row_major> af;
            wmma::load_matrix_sync(af, &Qs[wid * 16][k8], 36);
#pragma unroll
            for (int ni = 0; ni < 4; ni++) {
                wmma::fragment<wmma::matrix_b, 16, 16, 8, wmma::precision::tf32, wmma::col_major> bf;
                wmma::load_matrix_sync(bf, &Ks[ni * 16][k8], 36);
                wmma::mma_sync(sfr[ni], af, bf, sfr[ni]);
            }
        }
#pragma unroll
        for (int ni = 0; ni < 4; ni++)
            wmma::store_matrix_sync(&Ss[wid * 16][ni * 16], sfr[ni], 68, wmma::mem_row_major);
        __syncthreads();

        const float* brow = g_bias + (size_t)(bL + m0 + myrow) * Lc + k0 + myhalf;
        float* srow = &Ss[myrow][myhalf];
#pragma unroll
        for (int i = 0; i < 32; i += 4) {
            float4 bb = *reinterpret_cast<const float4*>(brow + i);
            float s0 = srow[i + 0] + bb.x; if (maskS[myhalf + i + 0] <= 0.f) s0 = -1e9f;
            float s1 = srow[i + 1] + bb.y; if (maskS[myhalf + i + 1] <= 0.f) s1 = -1e9f;
            float s2 = srow[i + 2] + bb.z; if (maskS[myhalf + i + 2] <= 0.f) s2 = -1e9f;
            float s3 = srow[i + 3] + bb.w; if (maskS[myhalf + i + 3] <= 0.f) s3 = -1e9f;
            float p0 = __expf(s0 - m_final);
            float p1 = __expf(s1 - m_final);
            float p2 = __expf(s2 - m_final);
            float p3 = __expf(s3 - m_final);
            myl += (p0 + p1) + (p2 + p3);
            srow[i + 0] = to_tf32(p0);
            srow[i + 1] = to_tf32(p1);
            srow[i + 2] = to_tf32(p2);
            srow[i + 3] = to_tf32(p3);
        }
        __syncthreads();

#pragma unroll
        for (int k8 = 0; k8 < 64; k8 += 8) {
            wmma::fragment<wmma::matrix_a, 16, 16, 8, wmma::precision::tf32, wmma::row_major> af;
            wmma::load_matrix_sync(af, &Ss[wid * 16][k8], 68);
#pragma unroll
            for (int ni = 0; ni < 2; ni++) {
                wmma::fragment<wmma::matrix_b, 16, 16, 8, wmma::precision::tf32, wmma::row_major> bf;
                wmma::load_matrix_sync(bf, &Vs[k8][ni * 16], 36);
                wmma::mma_sync(ofr[ni], af, bf, ofr[ni]);
            }
        }
        __syncthreads();
    }

    rowl[myrow][t & 1] = myl;
    wmma::store_matrix_sync(&Ss[wid * 16][0], ofr[0], 68, wmma::mem_row_major);
    wmma::store_matrix_sync(&Ss[wid * 16][16], ofr[1], 68, wmma::mem_row_major);
    __syncthreads();
    float linv = 1.f / (rowl[myrow][0] + rowl[myrow][1]);
    // O tile is 64 x 32 (DKc); two threads per row -> each writes a 16-col half
    int myq = (t & 1) * 16;
    float* op = g_ctx + (size_t)(bL + m0 + myrow) * Dc + h * DKc + myq;
#pragma unroll
    for (int i = 0; i < 16; i += 4) {
        float4 o;
        o.x = Ss[myrow][myq + i + 0] * linv;
        o.y = Ss[myrow][myq + i + 1] * linv;
        o.z = Ss[myrow][myq + i + 2] * linv;
        o.w = Ss[myrow][myq + i + 3] * linv;
        *reinterpret_cast<float4*>(op + i) = o;
    }
}

// ---------------- LN1: h_V_new = LN(h_V + ctx@Wo+bo) * mask ----------------
__global__ void ln1_kernel(const float* __restrict__ hV,
                           const float* __restrict__ gvec, const float* __restrict__ bvec,
                           const float* __restrict__ mask, float* __restrict__ out) {
    __shared__ float sh[8];
    int row = blockIdx.x, t = threadIdx.x;
    float x = hV[row * Dc + t] + g_tmp[row * Dc + t];
    float mean = blockSum(x, sh) * (1.f / Dc);
    float d = x - mean;
    float var = blockSum(d * d, sh) * (1.f / Dc);
    float y = d * rsqrtf(var + 1e-5f) * gvec[t] + bvec[t];
    out[row * Dc + t] = y * mask[row];
}

// ------- LN2 vectorized: h_E = LN(E + m1_raw + b13); 4 rows/block, float4 -------
__global__ void __launch_bounds__(256)
ln2v_kernel(const float* __restrict__ Ein,
            const float* __restrict__ b13,
            const float* __restrict__ gvec, const float* __restrict__ bvec,
            float* __restrict__ out) {
    __shared__ float s1[4][2], s2[4][2];
    int t = threadIdx.x;
    int rb = t >> 6;              // row in block 0..3
    int l6 = t & 63;              // lane within row
    int w2 = (t >> 5) & 1;        // warp-half within row
    size_t row = (size_t)blockIdx.x * 4 + rb;
    int c = l6 * 4;
    float4 e = *reinterpret_cast<const float4*>(Ein + row * Dc + c);
    float4 m = *reinterpret_cast<const float4*>(g_m1 + row * Dc + c);
    float4 bb = *reinterpret_cast<const float4*>(b13 + c);
    float x0 = e.x + m.x + bb.x;
    float x1 = e.y + m.y + bb.y;
    float x2 = e.z + m.z + bb.z;
    float x3 = e.w + m.w + bb.w;
    float sum = (x0 + x1) + (x2 + x3);
    float sq = x0 * x0 + x1 * x1 + x2 * x2 + x3 * x3;
#pragma unroll
    for (int o = 16; o; o >>= 1) {
        sum += __shfl_down_sync(0xffffffffu, sum, o);
        sq  += __shfl_down_sync(0xffffffffu, sq, o);
    }
    if ((t & 31) == 0) { s1[rb][w2] = sum; s2[rb][w2] = sq; }
    __syncthreads();
    float tot = s1[rb][0] + s1[rb][1];
    float tsq = s2[rb][0] + s2[rb][1];
    float mean = tot * (1.f / Dc);
    float var = tsq * (1.f / Dc) - mean * mean;
    float inv = rsqrtf(var + 1e-5f);
    float4 g4 = *reinterpret_cast<const float4*>(gvec + c);
    float4 b4 = *reinterpret_cast<const float4*>(bvec + c);
    float4 o;
    o.x = (x0 - mean) * inv * g4.x + b4.x;
    o.y = (x1 - mean) * inv * g4.y + b4.y;
    o.z = (x2 - mean) * inv * g4.z + b4.z;
    o.w = (x3 - mean) * inv * g4.w + b4.w;
    *reinterpret_cast<float4*>(out + row * Dc + c) = o;
}

// ---------------- host launch ----------------
extern "C" void kernel_launch(void* const* d_in, const int* in_sizes, int n_in,
                              void* d_out, int out_size) {
    const float* h_V    = (const float*)d_in[0];
    const float* E      = (const float*)d_in[1];
    const int*   E_idx  = (const int*)  d_in[2];
    const float* mask   = (const float*)d_in[3];
    const float* nonE   = (const float*)d_in[4];
    const float* bias_W = (const float*)d_in[5];
    const float* bias_b = (const float*)d_in[6];
    const float* Wq = (const float*)d_in[7];  const float* bq = (const float*)d_in[8];
    const float* Wk = (const float*)d_in[9];  const float* bk = (const float*)d_in[10];
    const float* Wv = (const float*)d_in[11]; const float* bv = (const float*)d_in[12];
    const float* Wo = (const float*)d_in[13]; const float* bo = (const float*)d_in[14];
    const float* ln1g = (const float*)d_in[15]; const float* ln1b = (const float*)d_in[16];
    const float* W11 = (const float*)d_in[17]; const float* b11 = (const float*)d_in[18];
    const float* W12 = (const float*)d_in[19]; const float* b12 = (const float*)d_in[20];
    const float* W13 = (const float*)d_in[21]; const float* b13 = (const float*)d_in[22];
    const float* ln2g = (const float*)d_in[23]; const float* ln2b = (const float*)d_in[24];

    float* out_hV = (float*)d_out;
    float* out_hE = out_hV + M1c * Dc;

    float *p_q, *p_k, *p_v, *p_ctx, *p_tmp, *p_hvp, *p_m1, *p_m2;
    cudaGetSymbolAddress((void**)&p_q,   g_q);
    cudaGetSymbolAddress((void**)&p_k,   g_k);
    cudaGetSymbolAddress((void**)&p_v,   g_v);
    cudaGetSymbolAddress((void**)&p_ctx, g_ctx);
    cudaGetSymbolAddress((void**)&p_tmp, g_tmp);
    cudaGetSymbolAddress((void**)&p_hvp, g_hvp);
    cudaGetSymbolAddress((void**)&p_m1,  g_m1);
    cudaGetSymbolAddress((void**)&p_m2,  g_m2);

    // attention bias
    bias_base_kernel<<<1, 256>>>(nonE, bias_W, bias_b);
    bias_fill_kernel<<<(Bc * Lc * Lc) / 256, 256>>>();
    bias_scatter_kernel<<<(Bc * Lc) / 8, 256>>>(E, E_idx, bias_W, bias_b);

    // qkv
    dim3 gqkv(Dc / 64, M1c / 64);
    gemm64<<<gqkv, 256>>>(h_V, Wq, p_q, M1c, Dc, Dc, bq, 0);
    gemm64<<<gqkv, 256>>>(h_V, Wk, p_k, M1c, Dc, Dc, bk, 0);
    gemm64<<<gqkv, 256>>>(h_V, Wv, p_v, M1c, Dc, Dc, bv, 0);

    // fused flash attention -> g_ctx
    flash_kernel<<<dim3(Lc / 64, Bc * Hc), 128>>>(mask);

    // out proj + LN1 (writes h_V_new into d_out)
    gemm64<<<gqkv, 256>>>(p_ctx, Wo, p_tmp, M1c, Dc, Dc, bo, 0);
    ln1_kernel<<<M1c, 256>>>(h_V, ln1g, ln1b, mask, out_hV);

    // MLP (tensor-core tf32, raw-acc stores, bias+gelu fused into next consumer's load)
    gemm64<<<gqkv, 256>>>(out_hV, W11, p_hvp, M1c, Dc, Dc, b11, 0);
    dim3 gbig(Dc / 128, M2c / 128);
    layer1_tc<<<gbig, 256>>>(E, E_idx, out_hV, W11);                 // m1 = raw
    gemm_tc<1><<<gbig, 256>>>(p_m1, W12, p_m2, M2c, Dc, Dc, p_hvp); // m2 = gelu(m1+hvp) @ W12 (raw)
    gemm_tc<2><<<gbig, 256>>>(p_m2, W13, p_m1, M2c, Dc, Dc, b12);   // m1 = gelu(m2+b12) @ W13 (raw)
    ln2v_kernel<<<M2c / 4, 256>>>(E, b13, ln2g, ln2b, out_hE);
}